// round 4
// baseline (speedup 1.0000x reference)
#include <cuda_runtime.h>

// Problem shape (fixed by dataset): 100000 nodes, 3.2M edges, 256 -> 32 -> 16x2
#define F0 256
#define F1 32
#define F2 16
#define MAXN 100000
#define MAXE 3200000
#define KT 32
#define GROWS 256
#define NB 296            // persistent grid (all resident: <= 2/SM on 148+ SMs)
#define GB 148            // blocks doing gemm in the split phase
#define THREADS 256
#define CHUNK 512         // scan chunk per block

// Scratch (allocation-free rule: __device__ globals)
__device__ __align__(16) float  g_dinv[MAXN];
__device__ int    g_degcnt[MAXN];
__device__ int    g_off[MAXN + 1];
__device__ int    g_cursor[MAXN];
__device__ int    g_bsum[NB];
__device__ __align__(16) float2 g_csr[MAXE];     // (src bits, weight)
__device__ __align__(16) float  g_hx[MAXN * F1];
__device__ __align__(16) float  g_h [MAXN * F1];

// grid barrier state (module-load zeroed; generation is monotonic across
// replays, count self-resets -> deterministic & graph-replay safe)
__device__ unsigned g_cnt;
__device__ unsigned g_gen;

__device__ __forceinline__ void gridbar() {
    __syncthreads();
    if (threadIdx.x == 0) {
        unsigned old = *(volatile unsigned*)&g_gen;
        __threadfence();
        if (atomicAdd(&g_cnt, 1u) == NB - 1) {
            g_cnt = 0;
            __threadfence();
            *(volatile unsigned*)&g_gen = old + 1;
        } else {
            while (*(volatile unsigned*)&g_gen == old) __nanosleep(32);
        }
    }
    __syncthreads();
}

// inclusive scan of p over the 256-thread block (ws: 8+ ints of smem)
__device__ __forceinline__ int block_incl_scan(int p, int* ws) {
    int lane = threadIdx.x & 31, wid = threadIdx.x >> 5;
    int v = p;
#pragma unroll
    for (int o = 1; o < 32; o <<= 1) {
        int u = __shfl_up_sync(0xffffffffu, v, o);
        if (lane >= o) v += u;
    }
    if (lane == 31) ws[wid] = v;
    __syncthreads();
    if (wid == 0) {
        int s = (lane < 8) ? ws[lane] : 0;
#pragma unroll
        for (int o = 1; o < 8; o <<= 1) {
            int u = __shfl_up_sync(0xffffffffu, s, o);
            if (lane >= o) s += u;
        }
        if (lane < 8) ws[lane] = s;
    }
    __syncthreads();
    return v + (wid ? ws[wid - 1] : 0);
}

__global__ void __launch_bounds__(THREADS, 2) mega_kernel(
        const float* __restrict__ x,  const int* __restrict__ ei,
        const float* __restrict__ W1, const float* __restrict__ b1,
        const float* __restrict__ Wm, const float* __restrict__ bm,
        const float* __restrict__ Wv, const float* __restrict__ bv,
        float* __restrict__ out, int n, int E) {
    __shared__ union {
        struct { float xs[GROWS * (KT + 1)]; float Wts[KT * F1]; } g;   // 37.9 KB
        struct { float Wms[F1 * F2]; float Wvs[F1 * F2]; float ts[8][F1]; } e;
        int ws[32];
    } sm;

    const int tid  = threadIdx.x;
    const int lane = tid & 31;
    const int gstride = NB * THREADS;
    const int gidx = blockIdx.x * THREADS + tid;
    const int nch = (n + CHUNK - 1) / CHUNK;     // 196 for n=100000

    // ---- P0: zero degree counters --------------------------------------
    for (int i = gidx; i < n; i += gstride) g_degcnt[i] = 0;
    gridbar();

    // ---- P1: in-degree over dst ----------------------------------------
    for (int e = gidx; e < E; e += gstride)
        atomicAdd(&g_degcnt[ei[E + e]], 1);
    gridbar();

    // ---- P2: dinv + per-chunk degree sums ------------------------------
    if (blockIdx.x < nch) {
        int base = blockIdx.x * CHUNK;
        int i0 = base + 2 * tid, i1 = i0 + 1;
        int a0 = (i0 < n) ? __ldcg(&g_degcnt[i0]) : 0;
        int a1 = (i1 < n) ? __ldcg(&g_degcnt[i1]) : 0;
        if (i0 < n) g_dinv[i0] = rsqrtf((float)a0 + 1.0f);
        if (i1 < n) g_dinv[i1] = rsqrtf((float)a1 + 1.0f);
        int incl = block_incl_scan(a0 + a1, sm.ws);
        if (tid == THREADS - 1) g_bsum[blockIdx.x] = incl;   // chunk total
    }
    gridbar();

    // ---- P3: exclusive scan of chunk totals (block 0) ------------------
    if (blockIdx.x == 0) {
        int v = (tid < nch) ? __ldcg(&g_bsum[tid]) : 0;
        int incl = block_incl_scan(v, sm.ws);
        if (tid < nch) g_bsum[tid] = incl - v;               // exclusive
    }
    gridbar();

    // ---- P4: per-chunk exclusive scan -> offsets + cursors -------------
    if (blockIdx.x < nch) {
        int base = blockIdx.x * CHUNK;
        int i0 = base + 2 * tid, i1 = i0 + 1;
        int a0 = (i0 < n) ? __ldcg(&g_degcnt[i0]) : 0;
        int a1 = (i1 < n) ? __ldcg(&g_degcnt[i1]) : 0;
        int p = a0 + a1;
        int incl = block_incl_scan(p, sm.ws);
        int ex = incl - p + __ldcg(&g_bsum[blockIdx.x]);
        if (i0 < n) { g_off[i0] = ex;      g_cursor[i0] = ex;      }
        if (i1 < n) { g_off[i1] = ex + a0; g_cursor[i1] = ex + a0; }
    }
    if (blockIdx.x == 0 && tid == 0) g_off[n] = E;
    gridbar();

    // ---- P5: gemm (blocks 0..GB-1) || csr fill (blocks GB..NB-1) -------
    if (blockIdx.x < GB) {
        int ntiles = (n + GROWS - 1) / GROWS;
        int cg = tid & 3;
        int rg = tid >> 2;
        for (int tile = blockIdx.x; tile < ntiles; tile += GB) {
            int row0 = tile * GROWS;
            float acc[4][8];
#pragma unroll
            for (int i = 0; i < 4; i++)
#pragma unroll
                for (int j = 0; j < 8; j++) acc[i][j] = 0.0f;

            for (int kt = 0; kt < F0; kt += KT) {
                __syncthreads();
                {
                    float4 w = *reinterpret_cast<const float4*>(
                        W1 + (size_t)kt * F1 + tid * 4);
                    *reinterpret_cast<float4*>(&sm.g.Wts[tid * 4]) = w;
                }
#pragma unroll
                for (int it = 0; it < 8; it++) {
                    int i = tid + it * 256;
                    int r = i >> 3;
                    int q = i & 7;
                    int grow = row0 + r;
                    float4 v = make_float4(0.f, 0.f, 0.f, 0.f);
                    if (grow < n)
                        v = *reinterpret_cast<const float4*>(
                            x + (size_t)grow * F0 + kt + q * 4);
                    float* dst = &sm.g.xs[r * (KT + 1) + q * 4];
                    dst[0] = v.x; dst[1] = v.y; dst[2] = v.z; dst[3] = v.w;
                }
                __syncthreads();

#pragma unroll
                for (int k = 0; k < KT; k++) {
                    float xv[4];
#pragma unroll
                    for (int i = 0; i < 4; i++)
                        xv[i] = sm.g.xs[(rg * 4 + i) * (KT + 1) + k];
                    float4 w0 = *reinterpret_cast<const float4*>(
                        &sm.g.Wts[k * F1 + cg * 8]);
                    float4 w1 = *reinterpret_cast<const float4*>(
                        &sm.g.Wts[k * F1 + cg * 8 + 4]);
#pragma unroll
                    for (int i = 0; i < 4; i++) {
                        acc[i][0] = fmaf(xv[i], w0.x, acc[i][0]);
                        acc[i][1] = fmaf(xv[i], w0.y, acc[i][1]);
                        acc[i][2] = fmaf(xv[i], w0.z, acc[i][2]);
                        acc[i][3] = fmaf(xv[i], w0.w, acc[i][3]);
                        acc[i][4] = fmaf(xv[i], w1.x, acc[i][4]);
                        acc[i][5] = fmaf(xv[i], w1.y, acc[i][5]);
                        acc[i][6] = fmaf(xv[i], w1.z, acc[i][6]);
                        acc[i][7] = fmaf(xv[i], w1.w, acc[i][7]);
                    }
                }
            }
#pragma unroll
            for (int i = 0; i < 4; i++) {
                int row = row0 + rg * 4 + i;
                if (row < n) {
                    float* dst = &g_hx[(size_t)row * F1 + cg * 8];
                    *reinterpret_cast<float4*>(dst) =
                        make_float4(acc[i][0], acc[i][1], acc[i][2], acc[i][3]);
                    *reinterpret_cast<float4*>(dst + 4) =
                        make_float4(acc[i][4], acc[i][5], acc[i][6], acc[i][7]);
                }
            }
        }
    } else {
        int fidx = (blockIdx.x - GB) * THREADS + tid;
        int fstride = (NB - GB) * THREADS;
        for (int e = fidx; e < E; e += fstride) {
            int src = ei[e];
            int dst = ei[E + e];
            int pos = atomicAdd(&g_cursor[dst], 1);
            g_csr[pos] = make_float2(__int_as_float(src),
                                     g_dinv[src] * g_dinv[dst]);
        }
    }
    gridbar();

    // ---- P6: gather layer 1 (warp per node) ----------------------------
    {
        int gw = gidx >> 5;
        int wstride = NB * (THREADS / 32);
        float bias = b1[lane];
        for (int node = gw; node < n; node += wstride) {
            int beg = g_off[node], end = g_off[node + 1];
            float acc0 = 0.f, acc1 = 0.f;
            int k = beg;
            if ((k & 1) && k < end) {
                float2 r = g_csr[k];
                acc0 = fmaf(g_hx[(size_t)__float_as_int(r.x) * F1 + lane],
                            r.y, acc0);
                k++;
            }
#pragma unroll 2
            for (; k + 2 <= end; k += 2) {
                float4 r = *reinterpret_cast<const float4*>(&g_csr[k]);
                acc0 = fmaf(g_hx[(size_t)__float_as_int(r.x) * F1 + lane],
                            r.y, acc0);
                acc1 = fmaf(g_hx[(size_t)__float_as_int(r.z) * F1 + lane],
                            r.w, acc1);
            }
            if (k < end) {
                float2 r = g_csr[k];
                acc0 = fmaf(g_hx[(size_t)__float_as_int(r.x) * F1 + lane],
                            r.y, acc0);
            }
            float d = g_dinv[node];
            float v = acc0 + acc1 + g_hx[(size_t)node * F1 + lane] * d * d + bias;
            g_h[(size_t)node * F1 + lane] = v > 0.f ? v : 0.f;
        }
    }
    gridbar();

    // ---- P7: gather layer 2 + fused mu/sigma epilogue ------------------
    {
        for (int i = tid; i < F1 * F2; i += THREADS) {
            sm.e.Wms[i] = Wm[i];
            sm.e.Wvs[i] = Wv[i];
        }
        __syncthreads();
        int gw = gidx >> 5;
        int wIn = tid >> 5;
        int wstride = NB * (THREADS / 32);
        int c = lane & 15;
        float biasv = (lane < 16) ? bm[c] : bv[c];
        for (int node = gw; node < n; node += wstride) {
            int beg = g_off[node], end = g_off[node + 1];
            float acc0 = 0.f, acc1 = 0.f;
            int k = beg;
            if ((k & 1) && k < end) {
                float2 r = g_csr[k];
                acc0 = fmaf(g_h[(size_t)__float_as_int(r.x) * F1 + lane],
                            r.y, acc0);
                k++;
            }
#pragma unroll 2
            for (; k + 2 <= end; k += 2) {
                float4 r = *reinterpret_cast<const float4*>(&g_csr[k]);
                acc0 = fmaf(g_h[(size_t)__float_as_int(r.x) * F1 + lane],
                            r.y, acc0);
                acc1 = fmaf(g_h[(size_t)__float_as_int(r.z) * F1 + lane],
                            r.w, acc1);
            }
            if (k < end) {
                float2 r = g_csr[k];
                acc0 = fmaf(g_h[(size_t)__float_as_int(r.x) * F1 + lane],
                            r.y, acc0);
            }
            float d = g_dinv[node];
            sm.e.ts[wIn][lane] =
                acc0 + acc1 + g_h[(size_t)node * F1 + lane] * d * d;
            __syncwarp();
            const float* Wp = (lane < 16) ? sm.e.Wms : sm.e.Wvs;
            float a = 0.f;
#pragma unroll
            for (int kk = 0; kk < F1; kk++)
                a = fmaf(sm.e.ts[wIn][kk], Wp[kk * F2 + c], a);
            a += biasv;
            size_t o = (lane < 16) ? ((size_t)node * F2 + c)
                                   : ((size_t)n * F2 + (size_t)node * F2 + c);
            out[o] = a;
            __syncwarp();
        }
    }
}

// ---------------------------------------------------------------------------
extern "C" void kernel_launch(void* const* d_in, const int* in_sizes, int n_in,
                              void* d_out, int out_size) {
    const float* x  = (const float*)d_in[0];
    const int*   ei = (const int*)  d_in[1];
    const float* W1 = (const float*)d_in[2];
    const float* b1 = (const float*)d_in[3];
    const float* Wm = (const float*)d_in[4];
    const float* bm = (const float*)d_in[5];
    const float* Wv = (const float*)d_in[6];
    const float* bv = (const float*)d_in[7];
    float* out = (float*)d_out;

    int n = in_sizes[0] / F0;      // 100000
    int E = in_sizes[1] / 2;       // 3200000

    mega_kernel<<<NB, THREADS>>>(x, ei, W1, b1, Wm, bm, Wv, bv, out, n, E);
}

// round 5
// speedup vs baseline: 1.5975x; 1.5975x over previous
#include <cuda_runtime.h>

// Problem shape (fixed by dataset): 100000 nodes, 3.2M edges, 256 -> 32 -> 16x2
#define F0 256
#define F1 32
#define F2 16
#define MAXN 100000
#define MAXE 3200000
#define KT 32
#define GROWS 256
#define SCAN_BLK 1024

// Scratch (allocation-free rule: __device__ globals)
__device__ __align__(16) float  g_dinv[MAXN];
__device__ int    g_degcnt[MAXN];
__device__ int    g_off[MAXN + 1];
__device__ int    g_cursor[MAXN];
__device__ int    g_bsum[(MAXN + SCAN_BLK - 1) / SCAN_BLK];
__device__ __align__(16) float2 g_csr[MAXE];     // (src bits, weight)
__device__ __align__(16) float  g_hx[MAXN * F1];
__device__ __align__(16) float  g_h [MAXN * F1];

// ---------------------------------------------------------------------------
__global__ void zero_kernel(int n) {
    int i = blockIdx.x * blockDim.x + threadIdx.x;
    if (i < n) g_degcnt[i] = 0;
}

// in-degree over dst = edge_index[1], 4 edges per thread via int4
__global__ void deg_kernel(const int* __restrict__ ei, int E) {
    int e = (blockIdx.x * blockDim.x + threadIdx.x) * 4;
    if (e + 3 < E) {
        int4 d = *reinterpret_cast<const int4*>(ei + E + e);
        atomicAdd(&g_degcnt[d.x], 1);
        atomicAdd(&g_degcnt[d.y], 1);
        atomicAdd(&g_degcnt[d.z], 1);
        atomicAdd(&g_degcnt[d.w], 1);
    } else {
        for (int k = e; k < E; k++) atomicAdd(&g_degcnt[ei[E + k]], 1);
    }
}

// ---- scan1: per-block exclusive scan of degcnt (shuffle-based) + dinv -----
__global__ void __launch_bounds__(SCAN_BLK) scan1_kernel(int n) {
    __shared__ int ws[32];
    int tid = threadIdx.x;
    int i = blockIdx.x * SCAN_BLK + tid;
    int lane = tid & 31, wid = tid >> 5;
    int v = (i < n) ? g_degcnt[i] : 0;
    if (i < n) g_dinv[i] = rsqrtf((float)v + 1.0f);
    int s = v;
#pragma unroll
    for (int o = 1; o < 32; o <<= 1) {
        int u = __shfl_up_sync(0xffffffffu, s, o);
        if (lane >= o) s += u;
    }
    if (lane == 31) ws[wid] = s;
    __syncthreads();
    if (wid == 0) {
        int t = ws[lane];
#pragma unroll
        for (int o = 1; o < 32; o <<= 1) {
            int u = __shfl_up_sync(0xffffffffu, t, o);
            if (lane >= o) t += u;
        }
        ws[lane] = t;
    }
    __syncthreads();
    int pre = wid ? ws[wid - 1] : 0;
    if (i < n) g_off[i] = s - v + pre;            // exclusive within block
    if (tid == 0) g_bsum[blockIdx.x] = ws[31];    // block total
}

__global__ void scan2_kernel(int nb) {   // nb <= 128
    __shared__ int ws[4];
    int tid = threadIdx.x;               // 128 threads
    int lane = tid & 31, wid = tid >> 5;
    int v = (tid < nb) ? g_bsum[tid] : 0;
    int s = v;
#pragma unroll
    for (int o = 1; o < 32; o <<= 1) {
        int u = __shfl_up_sync(0xffffffffu, s, o);
        if (lane >= o) s += u;
    }
    if (lane == 31) ws[wid] = s;
    __syncthreads();
    int pre = 0;
    for (int w = 0; w < wid; w++) pre += ws[w];
    if (tid < nb) g_bsum[tid] = s - v + pre;      // exclusive
}

__global__ void scan3_kernel(int n, int E) {
    int i = blockIdx.x * blockDim.x + threadIdx.x;
    if (i < n) {
        int o = g_off[i] + g_bsum[i >> 10];
        g_off[i] = o;
        g_cursor[i] = o;
    }
    if (i == 0) g_off[n] = E;
}

// ---- CSR fill: 4 edges per thread, int4 edge reads ------------------------
__global__ void fill_kernel(const int* __restrict__ ei, int E) {
    int e = (blockIdx.x * blockDim.x + threadIdx.x) * 4;
    if (e + 3 < E) {
        int4 s = *reinterpret_cast<const int4*>(ei + e);
        int4 d = *reinterpret_cast<const int4*>(ei + E + e);
        float ds0 = g_dinv[s.x], dd0 = g_dinv[d.x];
        float ds1 = g_dinv[s.y], dd1 = g_dinv[d.y];
        float ds2 = g_dinv[s.z], dd2 = g_dinv[d.z];
        float ds3 = g_dinv[s.w], dd3 = g_dinv[d.w];
        int p0 = atomicAdd(&g_cursor[d.x], 1);
        int p1 = atomicAdd(&g_cursor[d.y], 1);
        int p2 = atomicAdd(&g_cursor[d.z], 1);
        int p3 = atomicAdd(&g_cursor[d.w], 1);
        g_csr[p0] = make_float2(__int_as_float(s.x), ds0 * dd0);
        g_csr[p1] = make_float2(__int_as_float(s.y), ds1 * dd1);
        g_csr[p2] = make_float2(__int_as_float(s.z), ds2 * dd2);
        g_csr[p3] = make_float2(__int_as_float(s.w), ds3 * dd3);
    } else {
        for (int k = e; k < E; k++) {
            int src = ei[k], dst = ei[E + k];
            int pos = atomicAdd(&g_cursor[dst], 1);
            g_csr[pos] = make_float2(__int_as_float(src),
                                     g_dinv[src] * g_dinv[dst]);
        }
    }
}

// ---------------------------------------------------------------------------
// hx = x @ W1  (N x 256  @  256 x 32), register-tiled (proven).
__global__ void __launch_bounds__(256) gemm1_kernel(
        const float* __restrict__ x, const float* __restrict__ W1, int n) {
    __shared__ float xs[GROWS * (KT + 1)];
    __shared__ float Wts[KT * F1];

    int tid = threadIdx.x;
    int cg = tid & 3;
    int rg = tid >> 2;
    int row0 = blockIdx.x * GROWS;

    float acc[4][8];
#pragma unroll
    for (int i = 0; i < 4; i++)
#pragma unroll
        for (int j = 0; j < 8; j++) acc[i][j] = 0.0f;

    for (int kt = 0; kt < F0; kt += KT) {
        __syncthreads();
        {
            float4 w = *reinterpret_cast<const float4*>(W1 + (size_t)kt * F1 + tid * 4);
            *reinterpret_cast<float4*>(&Wts[tid * 4]) = w;
        }
#pragma unroll
        for (int it = 0; it < 8; it++) {
            int i = tid + it * 256;
            int r = i >> 3;
            int q = i & 7;
            int grow = row0 + r;
            float4 v = make_float4(0.f, 0.f, 0.f, 0.f);
            if (grow < n)
                v = *reinterpret_cast<const float4*>(x + (size_t)grow * F0 + kt + q * 4);
            float* dst = &xs[r * (KT + 1) + q * 4];
            dst[0] = v.x; dst[1] = v.y; dst[2] = v.z; dst[3] = v.w;
        }
        __syncthreads();

#pragma unroll
        for (int k = 0; k < KT; k++) {
            float xv[4];
#pragma unroll
            for (int i = 0; i < 4; i++)
                xv[i] = xs[(rg * 4 + i) * (KT + 1) + k];
            float4 w0 = *reinterpret_cast<const float4*>(&Wts[k * F1 + cg * 8]);
            float4 w1 = *reinterpret_cast<const float4*>(&Wts[k * F1 + cg * 8 + 4]);
#pragma unroll
            for (int i = 0; i < 4; i++) {
                acc[i][0] = fmaf(xv[i], w0.x, acc[i][0]);
                acc[i][1] = fmaf(xv[i], w0.y, acc[i][1]);
                acc[i][2] = fmaf(xv[i], w0.z, acc[i][2]);
                acc[i][3] = fmaf(xv[i], w0.w, acc[i][3]);
                acc[i][4] = fmaf(xv[i], w1.x, acc[i][4]);
                acc[i][5] = fmaf(xv[i], w1.y, acc[i][5]);
                acc[i][6] = fmaf(xv[i], w1.z, acc[i][6]);
                acc[i][7] = fmaf(xv[i], w1.w, acc[i][7]);
            }
        }
    }

#pragma unroll
    for (int i = 0; i < 4; i++) {
        int row = row0 + rg * 4 + i;
        if (row < n) {
            float* dst = &g_hx[(size_t)row * F1 + cg * 8];
            *reinterpret_cast<float4*>(dst) =
                make_float4(acc[i][0], acc[i][1], acc[i][2], acc[i][3]);
            *reinterpret_cast<float4*>(dst + 4) =
                make_float4(acc[i][4], acc[i][5], acc[i][6], acc[i][7]);
        }
    }
}

// ---------------------------------------------------------------------------
// Gather core: uniform float4 loads over CSR (2 records/load), 4 accumulators.
// Returns sum_e w_e * feat[src_e][lane] for one node.
__device__ __forceinline__ float gather_node(
        const float* __restrict__ feat, int beg, int end, int lane) {
    float a0 = 0.f, a1 = 0.f, a2 = 0.f, a3 = 0.f;
    int k = beg;
    if ((k & 1) && k < end) {
        float2 r = g_csr[k];
        a0 = fmaf(feat[__float_as_int(r.x) * F1 + lane], r.y, a0);
        k++;
    }
    for (; k + 4 <= end; k += 4) {
        float4 r0 = *reinterpret_cast<const float4*>(&g_csr[k]);
        float4 r1 = *reinterpret_cast<const float4*>(&g_csr[k + 2]);
        a0 = fmaf(feat[__float_as_int(r0.x) * F1 + lane], r0.y, a0);
        a1 = fmaf(feat[__float_as_int(r0.z) * F1 + lane], r0.w, a1);
        a2 = fmaf(feat[__float_as_int(r1.x) * F1 + lane], r1.y, a2);
        a3 = fmaf(feat[__float_as_int(r1.z) * F1 + lane], r1.w, a3);
    }
    if (k + 2 <= end) {
        float4 r0 = *reinterpret_cast<const float4*>(&g_csr[k]);
        a0 = fmaf(feat[__float_as_int(r0.x) * F1 + lane], r0.y, a0);
        a1 = fmaf(feat[__float_as_int(r0.z) * F1 + lane], r0.w, a1);
        k += 2;
    }
    if (k < end) {
        float2 r = g_csr[k];
        a2 = fmaf(feat[__float_as_int(r.x) * F1 + lane], r.y, a2);
    }
    return (a0 + a1) + (a2 + a3);
}

// Gather layer 1: one warp per node, lane = feature col.
__global__ void __launch_bounds__(256) gather1_kernel(
        const float* __restrict__ b1, int n) {
    int node = (blockIdx.x * blockDim.x + threadIdx.x) >> 5;
    int lane = threadIdx.x & 31;
    if (node >= n) return;
    int beg = g_off[node];
    int end = g_off[node + 1];
    float acc = gather_node(g_hx, beg, end, lane);
    float d = g_dinv[node];
    float v = acc + g_hx[node * F1 + lane] * d * d + b1[lane];
    g_h[node * F1 + lane] = v > 0.f ? v : 0.f;
}

// Gather layer 2 + fused mu/sigma epilogue.
__global__ void __launch_bounds__(256) gather2_kernel(
        const float* __restrict__ Wm, const float* __restrict__ bm,
        const float* __restrict__ Wv, const float* __restrict__ bv,
        float* __restrict__ out, int n) {
    __shared__ float Wms[F1 * F2];
    __shared__ float Wvs[F1 * F2];
    __shared__ float ts[8][F1];
    for (int i = threadIdx.x; i < F1 * F2; i += blockDim.x) {
        Wms[i] = Wm[i];
        Wvs[i] = Wv[i];
    }
    __syncthreads();

    int wIn  = threadIdx.x >> 5;
    int lane = threadIdx.x & 31;
    int node = blockIdx.x * 8 + wIn;
    if (node >= n) return;

    int beg = g_off[node];
    int end = g_off[node + 1];
    float acc = gather_node(g_h, beg, end, lane);
    float d = g_dinv[node];
    ts[wIn][lane] = acc + g_h[node * F1 + lane] * d * d;
    __syncwarp();

    int c = lane & 15;
    const float* Wp = (lane < 16) ? Wms : Wvs;
    float a = 0.f;
#pragma unroll
    for (int kk = 0; kk < F1; kk++)
        a = fmaf(ts[wIn][kk], Wp[kk * F2 + c], a);
    a += (lane < 16) ? bm[c] : bv[c];
    size_t o = (lane < 16) ? ((size_t)node * F2 + c)
                           : ((size_t)n * F2 + (size_t)node * F2 + c);
    out[o] = a;
}

// ---------------------------------------------------------------------------
extern "C" void kernel_launch(void* const* d_in, const int* in_sizes, int n_in,
                              void* d_out, int out_size) {
    const float* x  = (const float*)d_in[0];
    const int*   ei = (const int*)  d_in[1];
    const float* W1 = (const float*)d_in[2];
    const float* b1 = (const float*)d_in[3];
    const float* Wm = (const float*)d_in[4];
    const float* bm = (const float*)d_in[5];
    const float* Wv = (const float*)d_in[6];
    const float* bv = (const float*)d_in[7];
    float* out = (float*)d_out;

    int n = in_sizes[0] / F0;      // 100000
    int E = in_sizes[1] / 2;       // 3200000
    int nb = (n + SCAN_BLK - 1) / SCAN_BLK;
    int e4blocks = ((E + 3) / 4 + 255) / 256;

    zero_kernel<<<(n + 255) / 256, 256>>>(n);
    deg_kernel<<<e4blocks, 256>>>(ei, E);
    scan1_kernel<<<nb, SCAN_BLK>>>(n);
    scan2_kernel<<<1, 128>>>(nb);
    scan3_kernel<<<(n + 255) / 256, 256>>>(n, E);
    fill_kernel<<<e4blocks, 256>>>(ei, E);
    gemm1_kernel<<<(n + GROWS - 1) / GROWS, 256>>>(x, W1, n);
    gather1_kernel<<<(n * 32 + 255) / 256, 256>>>(b1, n);
    gather2_kernel<<<(n + 7) / 8, 256>>>(Wm, bm, Wv, bv, out, n);
}

// round 6
// speedup vs baseline: 1.6686x; 1.0445x over previous
#include <cuda_runtime.h>

// Problem shape (fixed by dataset): 100000 nodes, 3.2M edges, 256 -> 32 -> 16x2
#define F0 256
#define F1 32
#define F2 16
#define MAXN 100000
#define MAXE 3200000
#define KT 32
#define GROWS 256
#define SCAN_BLK 1024
#define NBSUM 128         // >= nb = ceil(MAXN/SCAN_BLK) = 98
#define GEMMB 391         // gemm tiles = ceil(100000/256)

// Scratch (allocation-free rule: __device__ globals)
__device__ __align__(16) float  g_dinv[MAXN];
__device__ int    g_degcnt[MAXN];
__device__ int    g_off[MAXN + 1];
__device__ int    g_cursor[MAXN];
__device__ int    g_bsum[NBSUM];
__device__ __align__(16) float2 g_csr[MAXE];     // (src bits, weight)
__device__ __align__(16) float  g_hx[MAXN * F1];
__device__ __align__(16) float  g_h [MAXN * F1];

// ---------------------------------------------------------------------------
__global__ void zero_kernel(int n) {
    int i = blockIdx.x * blockDim.x + threadIdx.x;
    if (i < n) g_degcnt[i] = 0;
}

// in-degree over dst = edge_index[1], 4 edges per thread via int4
__global__ void deg_kernel(const int* __restrict__ ei, int E) {
    int e = (blockIdx.x * blockDim.x + threadIdx.x) * 4;
    if (e + 3 < E) {
        int4 d = *reinterpret_cast<const int4*>(ei + E + e);
        atomicAdd(&g_degcnt[d.x], 1);
        atomicAdd(&g_degcnt[d.y], 1);
        atomicAdd(&g_degcnt[d.z], 1);
        atomicAdd(&g_degcnt[d.w], 1);
    } else {
        for (int k = e; k < E; k++) atomicAdd(&g_degcnt[ei[E + k]], 1);
    }
}

// ---- scan1: per-block exclusive scan of degcnt (shuffle) + dinv -----------
__global__ void __launch_bounds__(SCAN_BLK) scan1_kernel(int n) {
    __shared__ int ws[32];
    int tid = threadIdx.x;
    int i = blockIdx.x * SCAN_BLK + tid;
    int lane = tid & 31, wid = tid >> 5;
    int v = (i < n) ? g_degcnt[i] : 0;
    if (i < n) g_dinv[i] = rsqrtf((float)v + 1.0f);
    int s = v;
#pragma unroll
    for (int o = 1; o < 32; o <<= 1) {
        int u = __shfl_up_sync(0xffffffffu, s, o);
        if (lane >= o) s += u;
    }
    if (lane == 31) ws[wid] = s;
    __syncthreads();
    if (wid == 0) {
        int t = ws[lane];
#pragma unroll
        for (int o = 1; o < 32; o <<= 1) {
            int u = __shfl_up_sync(0xffffffffu, t, o);
            if (lane >= o) t += u;
        }
        ws[lane] = t;
    }
    __syncthreads();
    int pre = wid ? ws[wid - 1] : 0;
    if (i < n) g_off[i] = s - v + pre;            // exclusive within block
    if (tid == 0) g_bsum[blockIdx.x] = ws[31];    // block total
}

// ---- scan3: redundant per-block scan of block sums + finalize offsets -----
__global__ void __launch_bounds__(256) scan3_kernel(int n, int E, int nb) {
    __shared__ int ws[8];
    __shared__ int sp[NBSUM];
    int tid = threadIdx.x;
    int lane = tid & 31, wid = tid >> 5;
    // inclusive scan of bsum over 256 threads (only nb meaningful)
    int v = (tid < nb) ? g_bsum[tid] : 0;
    int s = v;
#pragma unroll
    for (int o = 1; o < 32; o <<= 1) {
        int u = __shfl_up_sync(0xffffffffu, s, o);
        if (lane >= o) s += u;
    }
    if (lane == 31) ws[wid] = s;
    __syncthreads();
    if (wid == 0) {
        int t = (lane < 8) ? ws[lane] : 0;
#pragma unroll
        for (int o = 1; o < 8; o <<= 1) {
            int u = __shfl_up_sync(0xffffffffu, t, o);
            if (lane >= o) t += u;
        }
        if (lane < 8) ws[lane] = t;
    }
    __syncthreads();
    if (tid < nb) sp[tid] = s - v + (wid ? ws[wid - 1] : 0);  // exclusive
    __syncthreads();

    int i = blockIdx.x * 256 + tid;
    if (i < n) {
        int o = g_off[i] + sp[i >> 10];
        g_off[i] = o;
        g_cursor[i] = o;
    }
    if (i == 0) g_off[n] = E;
}

// ---------------------------------------------------------------------------
// Fused: blocks [0, GEMMB) do hx = x @ W1 (register-tiled, proven);
//        blocks [GEMMB, grid) do CSR fill (independent work).
__global__ void __launch_bounds__(256) gemmfill_kernel(
        const float* __restrict__ x, const float* __restrict__ W1,
        const int* __restrict__ ei, int n, int E, int fillb) {
    if (blockIdx.x >= GEMMB) {
        // ---- CSR fill ----
        int t = (blockIdx.x - GEMMB) * 256 + threadIdx.x;
        int stride = fillb * 256;
        for (int e = t; e < E; e += stride) {
            int src = ei[e];
            int dst = ei[E + e];
            int pos = atomicAdd(&g_cursor[dst], 1);
            g_csr[pos] = make_float2(__int_as_float(src),
                                     g_dinv[src] * g_dinv[dst]);
        }
        return;
    }
    // ---- GEMM tile ----
    __shared__ float xs[GROWS * (KT + 1)];
    __shared__ float Wts[KT * F1];

    int tid = threadIdx.x;
    int cg = tid & 3;
    int rg = tid >> 2;
    int row0 = blockIdx.x * GROWS;

    float acc[4][8];
#pragma unroll
    for (int i = 0; i < 4; i++)
#pragma unroll
        for (int j = 0; j < 8; j++) acc[i][j] = 0.0f;

    for (int kt = 0; kt < F0; kt += KT) {
        __syncthreads();
        {
            float4 w = *reinterpret_cast<const float4*>(W1 + (size_t)kt * F1 + tid * 4);
            *reinterpret_cast<float4*>(&Wts[tid * 4]) = w;
        }
#pragma unroll
        for (int it = 0; it < 8; it++) {
            int i = tid + it * 256;
            int r = i >> 3;
            int q = i & 7;
            int grow = row0 + r;
            float4 v = make_float4(0.f, 0.f, 0.f, 0.f);
            if (grow < n)
                v = *reinterpret_cast<const float4*>(x + (size_t)grow * F0 + kt + q * 4);
            float* dst = &xs[r * (KT + 1) + q * 4];
            dst[0] = v.x; dst[1] = v.y; dst[2] = v.z; dst[3] = v.w;
        }
        __syncthreads();

#pragma unroll
        for (int k = 0; k < KT; k++) {
            float xv[4];
#pragma unroll
            for (int i = 0; i < 4; i++)
                xv[i] = xs[(rg * 4 + i) * (KT + 1) + k];
            float4 w0 = *reinterpret_cast<const float4*>(&Wts[k * F1 + cg * 8]);
            float4 w1 = *reinterpret_cast<const float4*>(&Wts[k * F1 + cg * 8 + 4]);
#pragma unroll
            for (int i = 0; i < 4; i++) {
                acc[i][0] = fmaf(xv[i], w0.x, acc[i][0]);
                acc[i][1] = fmaf(xv[i], w0.y, acc[i][1]);
                acc[i][2] = fmaf(xv[i], w0.z, acc[i][2]);
                acc[i][3] = fmaf(xv[i], w0.w, acc[i][3]);
                acc[i][4] = fmaf(xv[i], w1.x, acc[i][4]);
                acc[i][5] = fmaf(xv[i], w1.y, acc[i][5]);
                acc[i][6] = fmaf(xv[i], w1.z, acc[i][6]);
                acc[i][7] = fmaf(xv[i], w1.w, acc[i][7]);
            }
        }
    }

#pragma unroll
    for (int i = 0; i < 4; i++) {
        int row = row0 + rg * 4 + i;
        if (row < n) {
            float* dst = &g_hx[(size_t)row * F1 + cg * 8];
            *reinterpret_cast<float4*>(dst) =
                make_float4(acc[i][0], acc[i][1], acc[i][2], acc[i][3]);
            *reinterpret_cast<float4*>(dst + 4) =
                make_float4(acc[i][4], acc[i][5], acc[i][6], acc[i][7]);
        }
    }
}

// ---------------------------------------------------------------------------
// Gather core (round-3 shfl pattern, widened to 4 accumulators + zero-pad).
__device__ __forceinline__ float gather_node(
        const float* __restrict__ feat, int beg, int end, int lane) {
    float a0 = 0.f, a1 = 0.f, a2 = 0.f, a3 = 0.f;
    for (int k = beg; k < end; k += 32) {
        int cnt = end - k;
        if (cnt > 32) cnt = 32;
        float2 rec = make_float2(__int_as_float(0), 0.f);  // pad: w=0 -> no-op
        if (lane < cnt) rec = g_csr[k + lane];
        int   src = __float_as_int(rec.x);
        float w   = rec.y;
        int cm = (cnt + 3) & ~3;
        for (int j = 0; j < cm; j += 4) {
            int   s0 = __shfl_sync(0xffffffffu, src, j);
            float w0 = __shfl_sync(0xffffffffu, w,   j);
            int   s1 = __shfl_sync(0xffffffffu, src, j + 1);
            float w1 = __shfl_sync(0xffffffffu, w,   j + 1);
            int   s2 = __shfl_sync(0xffffffffu, src, j + 2);
            float w2 = __shfl_sync(0xffffffffu, w,   j + 2);
            int   s3 = __shfl_sync(0xffffffffu, src, j + 3);
            float w3 = __shfl_sync(0xffffffffu, w,   j + 3);
            a0 = fmaf(feat[s0 * F1 + lane], w0, a0);
            a1 = fmaf(feat[s1 * F1 + lane], w1, a1);
            a2 = fmaf(feat[s2 * F1 + lane], w2, a2);
            a3 = fmaf(feat[s3 * F1 + lane], w3, a3);
        }
    }
    return (a0 + a1) + (a2 + a3);
}

// Gather layer 1: one warp per node, lane = feature col.
__global__ void __launch_bounds__(256) gather1_kernel(
        const float* __restrict__ b1, int n) {
    int node = (blockIdx.x * blockDim.x + threadIdx.x) >> 5;
    int lane = threadIdx.x & 31;
    if (node >= n) return;
    int beg = g_off[node];
    int end = g_off[node + 1];
    float acc = gather_node(g_hx, beg, end, lane);
    float d = g_dinv[node];
    float v = acc + g_hx[node * F1 + lane] * d * d + b1[lane];
    g_h[node * F1 + lane] = v > 0.f ? v : 0.f;
}

// Gather layer 2 + fused mu/sigma epilogue.
__global__ void __launch_bounds__(256) gather2_kernel(
        const float* __restrict__ Wm, const float* __restrict__ bm,
        const float* __restrict__ Wv, const float* __restrict__ bv,
        float* __restrict__ out, int n) {
    __shared__ float Wms[F1 * F2];
    __shared__ float Wvs[F1 * F2];
    __shared__ float ts[8][F1];
    for (int i = threadIdx.x; i < F1 * F2; i += blockDim.x) {
        Wms[i] = Wm[i];
        Wvs[i] = Wv[i];
    }
    __syncthreads();

    int wIn  = threadIdx.x >> 5;
    int lane = threadIdx.x & 31;
    int node = blockIdx.x * 8 + wIn;
    if (node >= n) return;

    int beg = g_off[node];
    int end = g_off[node + 1];
    float acc = gather_node(g_h, beg, end, lane);
    float d = g_dinv[node];
    ts[wIn][lane] = acc + g_h[node * F1 + lane] * d * d;
    __syncwarp();

    int c = lane & 15;
    const float* Wp = (lane < 16) ? Wms : Wvs;
    float a = 0.f;
#pragma unroll
    for (int kk = 0; kk < F1; kk++)
        a = fmaf(ts[wIn][kk], Wp[kk * F2 + c], a);
    a += (lane < 16) ? bm[c] : bv[c];
    size_t o = (lane < 16) ? ((size_t)node * F2 + c)
                           : ((size_t)n * F2 + (size_t)node * F2 + c);
    out[o] = a;
}

// ---------------------------------------------------------------------------
extern "C" void kernel_launch(void* const* d_in, const int* in_sizes, int n_in,
                              void* d_out, int out_size) {
    const float* x  = (const float*)d_in[0];
    const int*   ei = (const int*)  d_in[1];
    const float* W1 = (const float*)d_in[2];
    const float* b1 = (const float*)d_in[3];
    const float* Wm = (const float*)d_in[4];
    const float* bm = (const float*)d_in[5];
    const float* Wv = (const float*)d_in[6];
    const float* bv = (const float*)d_in[7];
    float* out = (float*)d_out;

    int n = in_sizes[0] / F0;      // 100000
    int E = in_sizes[1] / 2;       // 3200000
    int nb = (n + SCAN_BLK - 1) / SCAN_BLK;      // 98
    int e4blocks = ((E + 3) / 4 + 255) / 256;
    int fillb = 12109;                            // GEMMB + fillb = 12500

    zero_kernel<<<(n + 255) / 256, 256>>>(n);
    deg_kernel<<<e4blocks, 256>>>(ei, E);
    scan1_kernel<<<nb, SCAN_BLK>>>(n);
    scan3_kernel<<<(n + 255) / 256, 256>>>(n, E, nb);
    gemmfill_kernel<<<GEMMB + fillb, 256>>>(x, W1, ei, n, E, fillb);
    gather1_kernel<<<(n * 32 + 255) / 256, 256>>>(b1, n);
    gather2_kernel<<<(n + 7) / 8, 256>>>(Wm, bm, Wv, bv, out, n);
}

// round 7
// speedup vs baseline: 1.7618x; 1.0559x over previous
#include <cuda_runtime.h>

// Problem shape (fixed by dataset): 100000 nodes, 3.2M edges, 256 -> 32 -> 16x2
#define F0 256
#define F1 32
#define F2 16
#define MAXN 100000
#define MAXE 3200000
#define KT 32
#define GROWS 256
#define SCAN_BLK 1024
#define NBSUM 128         // >= nb = ceil(MAXN/SCAN_BLK) = 98
#define GEMMB 391         // gemm tiles = ceil(100000/256)

// Scratch (allocation-free rule: __device__ globals)
__device__ __align__(16) float  g_dinv[MAXN];
__device__ int    g_degcnt[MAXN];
__device__ int    g_off[MAXN + 1];
__device__ int    g_cursor[MAXN];
__device__ int    g_bsum[NBSUM];
__device__ __align__(16) float2 g_csr[MAXE];     // (src bits, weight)
__device__ __align__(16) float  g_hx[MAXN * F1];
__device__ __align__(16) float  g_h [MAXN * F1];

// ---------------------------------------------------------------------------
__global__ void zero_kernel(int n) {
    int i = blockIdx.x * blockDim.x + threadIdx.x;
    if (i < n) g_degcnt[i] = 0;
}

// in-degree over dst = edge_index[1], 4 edges per thread via int4
__global__ void deg_kernel(const int* __restrict__ ei, int E) {
    int e = (blockIdx.x * blockDim.x + threadIdx.x) * 4;
    if (e + 3 < E) {
        int4 d = *reinterpret_cast<const int4*>(ei + E + e);
        atomicAdd(&g_degcnt[d.x], 1);
        atomicAdd(&g_degcnt[d.y], 1);
        atomicAdd(&g_degcnt[d.z], 1);
        atomicAdd(&g_degcnt[d.w], 1);
    } else {
        for (int k = e; k < E; k++) atomicAdd(&g_degcnt[ei[E + k]], 1);
    }
}

// ---- scan1: per-block exclusive scan of degcnt (shuffle) + dinv -----------
__global__ void __launch_bounds__(SCAN_BLK) scan1_kernel(int n) {
    __shared__ int ws[32];
    int tid = threadIdx.x;
    int i = blockIdx.x * SCAN_BLK + tid;
    int lane = tid & 31, wid = tid >> 5;
    int v = (i < n) ? g_degcnt[i] : 0;
    if (i < n) g_dinv[i] = rsqrtf((float)v + 1.0f);
    int s = v;
#pragma unroll
    for (int o = 1; o < 32; o <<= 1) {
        int u = __shfl_up_sync(0xffffffffu, s, o);
        if (lane >= o) s += u;
    }
    if (lane == 31) ws[wid] = s;
    __syncthreads();
    if (wid == 0) {
        int t = ws[lane];
#pragma unroll
        for (int o = 1; o < 32; o <<= 1) {
            int u = __shfl_up_sync(0xffffffffu, t, o);
            if (lane >= o) t += u;
        }
        ws[lane] = t;
    }
    __syncthreads();
    int pre = wid ? ws[wid - 1] : 0;
    if (i < n) g_off[i] = s - v + pre;            // exclusive within block
    if (tid == 0) g_bsum[blockIdx.x] = ws[31];    // block total
}

// ---- scan3: redundant per-block scan of block sums + finalize offsets -----
__global__ void __launch_bounds__(256) scan3_kernel(int n, int E, int nb) {
    __shared__ int ws[8];
    __shared__ int sp[NBSUM];
    int tid = threadIdx.x;
    int lane = tid & 31, wid = tid >> 5;
    int v = (tid < nb) ? g_bsum[tid] : 0;
    int s = v;
#pragma unroll
    for (int o = 1; o < 32; o <<= 1) {
        int u = __shfl_up_sync(0xffffffffu, s, o);
        if (lane >= o) s += u;
    }
    if (lane == 31) ws[wid] = s;
    __syncthreads();
    if (wid == 0) {
        int t = (lane < 8) ? ws[lane] : 0;
#pragma unroll
        for (int o = 1; o < 8; o <<= 1) {
            int u = __shfl_up_sync(0xffffffffu, t, o);
            if (lane >= o) t += u;
        }
        if (lane < 8) ws[lane] = t;
    }
    __syncthreads();
    if (tid < nb) sp[tid] = s - v + (wid ? ws[wid - 1] : 0);  // exclusive
    __syncthreads();

    int i = blockIdx.x * 256 + tid;
    if (i < n) {
        int o = g_off[i] + sp[i >> 10];
        g_off[i] = o;
        g_cursor[i] = o;
    }
    if (i == 0) g_off[n] = E;
}

// ---------------------------------------------------------------------------
// Fused: blocks [0, GEMMB) do hx = x @ W1 (register-tiled, proven);
//        blocks [GEMMB, grid) do CSR fill (independent work).
__global__ void __launch_bounds__(256) gemmfill_kernel(
        const float* __restrict__ x, const float* __restrict__ W1,
        const int* __restrict__ ei, int n, int E, int fillb) {
    if (blockIdx.x >= GEMMB) {
        int t = (blockIdx.x - GEMMB) * 256 + threadIdx.x;
        int stride = fillb * 256;
        for (int e = t; e < E; e += stride) {
            int src = ei[e];
            int dst = ei[E + e];
            int pos = atomicAdd(&g_cursor[dst], 1);
            g_csr[pos] = make_float2(__int_as_float(src),
                                     g_dinv[src] * g_dinv[dst]);
        }
        return;
    }
    // ---- GEMM tile ----
    __shared__ float xs[GROWS * (KT + 1)];
    __shared__ float Wts[KT * F1];

    int tid = threadIdx.x;
    int cg = tid & 3;
    int rg = tid >> 2;
    int row0 = blockIdx.x * GROWS;

    float acc[4][8];
#pragma unroll
    for (int i = 0; i < 4; i++)
#pragma unroll
        for (int j = 0; j < 8; j++) acc[i][j] = 0.0f;

    for (int kt = 0; kt < F0; kt += KT) {
        __syncthreads();
        {
            float4 w = *reinterpret_cast<const float4*>(W1 + (size_t)kt * F1 + tid * 4);
            *reinterpret_cast<float4*>(&Wts[tid * 4]) = w;
        }
#pragma unroll
        for (int it = 0; it < 8; it++) {
            int i = tid + it * 256;
            int r = i >> 3;
            int q = i & 7;
            int grow = row0 + r;
            float4 v = make_float4(0.f, 0.f, 0.f, 0.f);
            if (grow < n)
                v = *reinterpret_cast<const float4*>(x + (size_t)grow * F0 + kt + q * 4);
            float* dst = &xs[r * (KT + 1) + q * 4];
            dst[0] = v.x; dst[1] = v.y; dst[2] = v.z; dst[3] = v.w;
        }
        __syncthreads();

#pragma unroll
        for (int k = 0; k < KT; k++) {
            float xv[4];
#pragma unroll
            for (int i = 0; i < 4; i++)
                xv[i] = xs[(rg * 4 + i) * (KT + 1) + k];
            float4 w0 = *reinterpret_cast<const float4*>(&Wts[k * F1 + cg * 8]);
            float4 w1 = *reinterpret_cast<const float4*>(&Wts[k * F1 + cg * 8 + 4]);
#pragma unroll
            for (int i = 0; i < 4; i++) {
                acc[i][0] = fmaf(xv[i], w0.x, acc[i][0]);
                acc[i][1] = fmaf(xv[i], w0.y, acc[i][1]);
                acc[i][2] = fmaf(xv[i], w0.z, acc[i][2]);
                acc[i][3] = fmaf(xv[i], w0.w, acc[i][3]);
                acc[i][4] = fmaf(xv[i], w1.x, acc[i][4]);
                acc[i][5] = fmaf(xv[i], w1.y, acc[i][5]);
                acc[i][6] = fmaf(xv[i], w1.z, acc[i][6]);
                acc[i][7] = fmaf(xv[i], w1.w, acc[i][7]);
            }
        }
    }

#pragma unroll
    for (int i = 0; i < 4; i++) {
        int row = row0 + rg * 4 + i;
        if (row < n) {
            float* dst = &g_hx[(size_t)row * F1 + cg * 8];
            *reinterpret_cast<float4*>(dst) =
                make_float4(acc[i][0], acc[i][1], acc[i][2], acc[i][3]);
            *reinterpret_cast<float4*>(dst + 4) =
                make_float4(acc[i][4], acc[i][5], acc[i][6], acc[i][7]);
        }
    }
}

// ---------------------------------------------------------------------------
// Gather core — EXACT round-3 inner loop (proven fastest): fully-unrolled
// 32-edge tiles with compile-time shfl lanes, 2 accumulators, serial remainder.
__device__ __forceinline__ float gather_node(
        const float* __restrict__ feat, int beg, int end, int lane) {
    float acc0 = 0.f, acc1 = 0.f;
    int k = beg;
    for (; k + 32 <= end; k += 32) {
        float2 rec = g_csr[k + lane];
        int   src = __float_as_int(rec.x);
        float w   = rec.y;
#pragma unroll
        for (int j = 0; j < 32; j += 2) {
            int   s0 = __shfl_sync(0xffffffffu, src, j);
            float w0 = __shfl_sync(0xffffffffu, w,   j);
            int   s1 = __shfl_sync(0xffffffffu, src, j + 1);
            float w1 = __shfl_sync(0xffffffffu, w,   j + 1);
            acc0 = fmaf(feat[(size_t)s0 * F1 + lane], w0, acc0);
            acc1 = fmaf(feat[(size_t)s1 * F1 + lane], w1, acc1);
        }
    }
    int rem = end - k;
    if (rem > 0) {
        float2 rec = make_float2(__int_as_float(0), 0.f);
        if (lane < rem) rec = g_csr[k + lane];
        int   src = __float_as_int(rec.x);
        float w   = rec.y;
        for (int j = 0; j < rem; j++) {
            int   s0 = __shfl_sync(0xffffffffu, src, j);
            float w0 = __shfl_sync(0xffffffffu, w,   j);
            acc0 = fmaf(feat[(size_t)s0 * F1 + lane], w0, acc0);
        }
    }
    return acc0 + acc1;
}

// Gather layer 1: one warp per node, lane = feature col.
__global__ void __launch_bounds__(256) gather1_kernel(
        const float* __restrict__ b1, int n) {
    int node = (blockIdx.x * blockDim.x + threadIdx.x) >> 5;
    int lane = threadIdx.x & 31;
    if (node >= n) return;
    int beg = g_off[node];
    int end = g_off[node + 1];
    float acc = gather_node(g_hx, beg, end, lane);
    float d = g_dinv[node];
    float v = acc + g_hx[(size_t)node * F1 + lane] * d * d + b1[lane];
    g_h[(size_t)node * F1 + lane] = v > 0.f ? v : 0.f;
}

// Gather layer 2 + fused mu/sigma epilogue.
__global__ void __launch_bounds__(256) gather2_kernel(
        const float* __restrict__ Wm, const float* __restrict__ bm,
        const float* __restrict__ Wv, const float* __restrict__ bv,
        float* __restrict__ out, int n) {
    __shared__ float Wms[F1 * F2];
    __shared__ float Wvs[F1 * F2];
    __shared__ float ts[8][F1];
    for (int i = threadIdx.x; i < F1 * F2; i += blockDim.x) {
        Wms[i] = Wm[i];
        Wvs[i] = Wv[i];
    }
    __syncthreads();

    int wIn  = threadIdx.x >> 5;
    int lane = threadIdx.x & 31;
    int node = blockIdx.x * 8 + wIn;
    if (node >= n) return;

    int beg = g_off[node];
    int end = g_off[node + 1];
    float acc = gather_node(g_h, beg, end, lane);
    float d = g_dinv[node];
    ts[wIn][lane] = acc + g_h[(size_t)node * F1 + lane] * d * d;
    __syncwarp();

    int c = lane & 15;
    const float* Wp = (lane < 16) ? Wms : Wvs;
    float a = 0.f;
#pragma unroll
    for (int kk = 0; kk < F1; kk++)
        a = fmaf(ts[wIn][kk], Wp[kk * F2 + c], a);
    a += (lane < 16) ? bm[c] : bv[c];
    size_t o = (lane < 16) ? ((size_t)node * F2 + c)
                           : ((size_t)n * F2 + (size_t)node * F2 + c);
    out[o] = a;
}

// ---------------------------------------------------------------------------
extern "C" void kernel_launch(void* const* d_in, const int* in_sizes, int n_in,
                              void* d_out, int out_size) {
    const float* x  = (const float*)d_in[0];
    const int*   ei = (const int*)  d_in[1];
    const float* W1 = (const float*)d_in[2];
    const float* b1 = (const float*)d_in[3];
    const float* Wm = (const float*)d_in[4];
    const float* bm = (const float*)d_in[5];
    const float* Wv = (const float*)d_in[6];
    const float* bv = (const float*)d_in[7];
    float* out = (float*)d_out;

    int n = in_sizes[0] / F0;      // 100000
    int E = in_sizes[1] / 2;       // 3200000
    int nb = (n + SCAN_BLK - 1) / SCAN_BLK;      // 98
    int e4blocks = ((E + 3) / 4 + 255) / 256;
    int fillb = 12109;                            // GEMMB + fillb = 12500

    zero_kernel<<<(n + 255) / 256, 256>>>(n);
    deg_kernel<<<e4blocks, 256>>>(ei, E);
    scan1_kernel<<<nb, SCAN_BLK>>>(n);
    scan3_kernel<<<(n + 255) / 256, 256>>>(n, E, nb);
    gemmfill_kernel<<<GEMMB + fillb, 256>>>(x, W1, ei, n, E, fillb);
    gather1_kernel<<<(n * 32 + 255) / 256, 256>>>(b1, n);
    gather2_kernel<<<(n + 7) / 8, 256>>>(Wm, bm, Wv, bv, out, n);
}